// round 13
// baseline (speedup 1.0000x reference)
#include <cuda_runtime.h>
#include <math.h>

#define NS 100000
#define NQUAD (NS / 4)      // 25000 quads of 4 consecutive rows
#define H 128
#define NBLK 592            // 4 blocks/SM * 148 SMs (256-thread blocks, 32 warps/SM)
#define NTHREADS 256
#define WPB 8
#define TOTW (NBLK * WPB)   // 4736 warps

typedef unsigned long long ull;

// Per-block partials: 0:t_mu+ 1:t_mu- 2:t_sig+ 3:t_sig- 4:S+ 5:S-
__device__ float g_part[6][NBLK];
__device__ int g_count = 0;

__device__ __forceinline__ ull ff2(ull a, ull b, ull c) {
    ull r;
    asm("fma.rn.f32x2 %0, %1, %2, %3;" : "=l"(r) : "l"(a), "l"(b), "l"(c));
    return r;
}
__device__ __forceinline__ ull pack2(float lo, float hi) {
    ull r;
    asm("mov.b64 %0, {%1, %2};" : "=l"(r) : "f"(lo), "f"(hi));
    return r;
}
__device__ __forceinline__ float sum2(ull a) {
    float lo, hi;
    asm("mov.b64 {%0, %1}, %2;" : "=f"(lo), "=f"(hi) : "l"(a));
    return lo + hi;
}
__device__ __forceinline__ float d4f(float4 a, float4 b) {
    return a.x * b.x + a.y * b.y + a.z * b.z + a.w * b.w;
}

__global__ __launch_bounds__(NTHREADS, 4) void fp_r13(
    const float* __restrict__ e, const float* __restrict__ q,
    const float* __restrict__ mu_w, const float* __restrict__ sigma_w,
    const float* __restrict__ w_key, const float* __restrict__ w_value,
    const float* __restrict__ mu_b, const float* __restrict__ sigma_b,
    float* __restrict__ out) {
    const int tid = threadIdx.x;
    const int lane = tid & 31;
    const int warp = tid >> 5;
    const int s = lane & 7;      // column slot within 8-lane row group
    const int g = lane >> 3;     // which of the 4 rows in the quad

    // mu_w / sigma_w fragments live in smem: [k][s], 16B per entry.
    // 8-lane LDS.128 phases cover banks 0-31 exactly; 4 row-groups broadcast.
    __shared__ ulonglong2 smf[4][8];
    __shared__ ulonglong2 ssf[4][8];
    __shared__ float wsum[WPB][6];
    __shared__ int is_last;

    if (tid < 32) {
        int k = tid >> 3, ss = tid & 7;
        float4 m = reinterpret_cast<const float4*>(mu_w)[ss + 8 * k];
        float4 w = reinterpret_cast<const float4*>(sigma_w)[ss + 8 * k];
        smf[k][ss] = make_ulonglong2(pack2(m.x, m.y), pack2(m.z, m.w));
        ssf[k][ss] = make_ulonglong2(pack2(w.x, w.y), pack2(w.z, w.w));
    }

    // q̂ fragment stays in registers (16 regs)
    const float4* __restrict__ q4p = reinterpret_cast<const float4*>(q);
    float4 qa = q4p[s], qb = q4p[s + 8], qc = q4p[s + 16], qe = q4p[s + 24];
    float qn = d4f(qa, qa) + d4f(qb, qb) + d4f(qc, qc) + d4f(qe, qe);
    qn += __shfl_xor_sync(0xffffffffu, qn, 1);
    qn += __shfl_xor_sync(0xffffffffu, qn, 2);
    qn += __shfl_xor_sync(0xffffffffu, qn, 4);
    const float rq = rsqrtf(qn);
    ull qf[8];
    qf[0] = pack2(qa.x * rq, qa.y * rq);  qf[1] = pack2(qa.z * rq, qa.w * rq);
    qf[2] = pack2(qb.x * rq, qb.y * rq);  qf[3] = pack2(qb.z * rq, qb.w * rq);
    qf[4] = pack2(qc.x * rq, qc.y * rq);  qf[5] = pack2(qc.z * rq, qc.w * rq);
    qf[6] = pack2(qe.x * rq, qe.y * rq);  qf[7] = pack2(qe.z * rq, qe.w * rq);

    __syncthreads();   // smf/ssf ready

    ull t0 = 0, t1 = 0, t2 = 0, t3 = 0;
    float spa = 0.f, sma = 0.f;

    const ulonglong2* __restrict__ e16 = reinterpret_cast<const ulonglong2*>(e);
    int qd = blockIdx.x * WPB + warp;
    const ulonglong2* rp = e16 + ((size_t)qd * 4 + g) * 32 + s;
    const size_t pstride = (size_t)TOTW * 4 * 32;
    for (; qd < NQUAD; qd += TOTW, rp += pstride) {
        ulonglong2 c0 = rp[0];
        ulonglong2 c1 = rp[8];
        ulonglong2 c2 = rp[16];
        ulonglong2 c3 = rp[24];

        ull d2 = 0, n2 = 0, m2 = 0, s2 = 0;
        {
            ulonglong2 mk = smf[0][s], sk = ssf[0][s];
            d2 = ff2(c0.x, qf[0], d2); n2 = ff2(c0.x, c0.x, n2);
            m2 = ff2(c0.x, mk.x, m2); s2 = ff2(c0.x, sk.x, s2);
            d2 = ff2(c0.y, qf[1], d2); n2 = ff2(c0.y, c0.y, n2);
            m2 = ff2(c0.y, mk.y, m2); s2 = ff2(c0.y, sk.y, s2);
        }
        {
            ulonglong2 mk = smf[1][s], sk = ssf[1][s];
            d2 = ff2(c1.x, qf[2], d2); n2 = ff2(c1.x, c1.x, n2);
            m2 = ff2(c1.x, mk.x, m2); s2 = ff2(c1.x, sk.x, s2);
            d2 = ff2(c1.y, qf[3], d2); n2 = ff2(c1.y, c1.y, n2);
            m2 = ff2(c1.y, mk.y, m2); s2 = ff2(c1.y, sk.y, s2);
        }
        {
            ulonglong2 mk = smf[2][s], sk = ssf[2][s];
            d2 = ff2(c2.x, qf[4], d2); n2 = ff2(c2.x, c2.x, n2);
            m2 = ff2(c2.x, mk.x, m2); s2 = ff2(c2.x, sk.x, s2);
            d2 = ff2(c2.y, qf[5], d2); n2 = ff2(c2.y, c2.y, n2);
            m2 = ff2(c2.y, mk.y, m2); s2 = ff2(c2.y, sk.y, s2);
        }
        {
            ulonglong2 mk = smf[3][s], sk = ssf[3][s];
            d2 = ff2(c3.x, qf[6], d2); n2 = ff2(c3.x, c3.x, n2);
            m2 = ff2(c3.x, mk.x, m2); s2 = ff2(c3.x, sk.x, s2);
            d2 = ff2(c3.y, qf[7], d2); n2 = ff2(c3.y, c3.y, n2);
            m2 = ff2(c3.y, mk.y, m2); s2 = ff2(c3.y, sk.y, s2);
        }

        float d = sum2(d2);
        float n = sum2(n2);
        d += __shfl_xor_sync(0xffffffffu, d, 1);
        n += __shfl_xor_sync(0xffffffffu, n, 1);
        d += __shfl_xor_sync(0xffffffffu, d, 2);
        n += __shfl_xor_sync(0xffffffffu, n, 2);
        d += __shfl_xor_sync(0xffffffffu, d, 4);
        n += __shfl_xor_sync(0xffffffffu, n, 4);

        float r = rsqrtf(n);
        float ap = fmaxf(d, 0.f) * r;
        float am = fmaxf(-d, 0.f) * r;
        spa += ap;
        sma += am;
        ull ap2 = pack2(ap, ap);
        ull am2 = pack2(am, am);
        t0 = ff2(ap2, m2, t0);
        t1 = ff2(am2, m2, t1);
        t2 = ff2(ap2, s2, t2);
        t3 = ff2(am2, s2, t3);
    }

    // ── warp epilogue ──
    float u0 = sum2(t0), u1 = sum2(t1), u2 = sum2(t2), u3 = sum2(t3);
#pragma unroll
    for (int o = 16; o > 0; o >>= 1) {
        u0 += __shfl_xor_sync(0xffffffffu, u0, o);
        u1 += __shfl_xor_sync(0xffffffffu, u1, o);
        u2 += __shfl_xor_sync(0xffffffffu, u2, o);
        u3 += __shfl_xor_sync(0xffffffffu, u3, o);
        spa += __shfl_xor_sync(0xffffffffu, spa, o);
        sma += __shfl_xor_sync(0xffffffffu, sma, o);
    }
    if (lane == 0) {
        wsum[warp][0] = u0;
        wsum[warp][1] = u1;
        wsum[warp][2] = u2;
        wsum[warp][3] = u3;
        wsum[warp][4] = spa * 0.125f;   // each row's a counted by its 8 lanes
        wsum[warp][5] = sma * 0.125f;
    }
    __syncthreads();
    if (tid < 6) {
        float acc = 0.f;
#pragma unroll
        for (int w = 0; w < WPB; w++) acc += wsum[w][tid];
        g_part[tid][blockIdx.x] = acc;
    }
    __threadfence();
    __syncthreads();
    if (tid == 0)
        is_last = (atomicAdd(&g_count, 1) == NBLK - 1) ? 1 : 0;
    __syncthreads();
    if (!is_last) return;

    // ── last block: final 6-scalar reduce + the 8 outputs ──
    __shared__ float tot[6];
    if (warp < 6) {
        float acc = 0.f;
#pragma unroll
        for (int i = 0; i < (NBLK + 31) / 32; i++) {
            int j = lane + i * 32;
            if (j < NBLK) acc += __ldcg(&g_part[warp][j]);
        }
#pragma unroll
        for (int o = 16; o > 0; o >>= 1)
            acc += __shfl_xor_sync(0xffffffffu, acc, o);
        if (lane == 0) tot[warp] = acc;
    }
    __syncthreads();
    if (tid < 4) {
        const float Sp = fmaxf(tot[4], 1e-6f);
        const float Sm = fmaxf(tot[5], 1e-6f);
        float wk = w_key[tid];
        float wv = w_value[tid];
        bool pos = (wk > 0.f);
        float dmu = pos ? (tot[0] / Sp) : (tot[1] / Sm);
        float dsg = pos ? (tot[2] / Sp) : (tot[3] / Sm);
        float mu_z = wv * dmu + mu_b[0];
        float x = wv * dsg + sigma_b[0];
        float sig_z = fmaxf(x, 0.f) + log1pf(expf(-fabsf(x)));
        out[tid] = mu_z;
        out[4 + tid] = sig_z;
    }
    if (tid == 0) g_count = 0;  // reset for next graph replay
}

extern "C" void kernel_launch(void* const* d_in, const int* in_sizes, int n_in,
                              void* d_out, int out_size) {
    const float* e       = (const float*)d_in[0];
    const float* w_key   = (const float*)d_in[1];
    const float* w_value = (const float*)d_in[2];
    const float* q       = (const float*)d_in[3];
    const float* mu_w    = (const float*)d_in[4];
    const float* mu_b    = (const float*)d_in[5];
    const float* sigma_w = (const float*)d_in[6];
    const float* sigma_b = (const float*)d_in[7];
    float* out = (float*)d_out;

    fp_r13<<<NBLK, NTHREADS>>>(e, q, mu_w, sigma_w, w_key, w_value, mu_b, sigma_b, out);
}

// round 14
// speedup vs baseline: 1.6318x; 1.6318x over previous
#include <cuda_runtime.h>
#include <math.h>

#define NS 100000
#define NQUAD (NS / 4)      // 25000 quads of 4 consecutive rows
#define H 128
#define NBLK 888            // 6 blocks/SM * 148 SMs (128-thread blocks, 24 warps/SM)
#define NTHREADS 128
#define WPB 4
#define TOTW (NBLK * WPB)   // 3552 warps

typedef unsigned long long ull;

// Per-block partials: 0:t_mu+ 1:t_mu- 2:t_sig+ 3:t_sig- 4:S+ 5:S-
__device__ float g_part[6][NBLK];
__device__ int g_count = 0;

__device__ __forceinline__ ull ff2(ull a, ull b, ull c) {
    ull r;
    asm("fma.rn.f32x2 %0, %1, %2, %3;" : "=l"(r) : "l"(a), "l"(b), "l"(c));
    return r;
}
__device__ __forceinline__ ull pack2(float lo, float hi) {
    ull r;
    asm("mov.b64 %0, {%1, %2};" : "=l"(r) : "f"(lo), "f"(hi));
    return r;
}
__device__ __forceinline__ float sum2(ull a) {
    float lo, hi;
    asm("mov.b64 {%0, %1}, %2;" : "=f"(lo), "=f"(hi) : "l"(a));
    return lo + hi;
}
__device__ __forceinline__ float d4f(float4 a, float4 b) {
    return a.x * b.x + a.y * b.y + a.z * b.z + a.w * b.w;
}
// dot of packed accumulator with a float4-pair fragment (as 2 ulls)
__device__ __forceinline__ ull dotfrag(ull acc, ull v, ull w, ull t) {
    t = ff2(acc, v, t);
    return t;
}

__global__ __launch_bounds__(NTHREADS, 6) void fp_r14(
    const float* __restrict__ e, const float* __restrict__ q,
    const float* __restrict__ mu_w, const float* __restrict__ sigma_w,
    const float* __restrict__ w_key, const float* __restrict__ w_value,
    const float* __restrict__ mu_b, const float* __restrict__ sigma_b,
    float* __restrict__ out) {
    const int tid = threadIdx.x;
    const int lane = tid & 31;
    const int warp = tid >> 5;
    const int s = lane & 7;      // column slot within 8-lane row group
    const int g = lane >> 3;     // which of the 4 rows in the quad

    // ── one-time fragment: q̂ only (16 regs). mu/sigma applied in epilogue. ──
    const float4* __restrict__ q4p = reinterpret_cast<const float4*>(q);
    float4 qa = q4p[s], qb = q4p[s + 8], qc = q4p[s + 16], qe = q4p[s + 24];
    float qn = d4f(qa, qa) + d4f(qb, qb) + d4f(qc, qc) + d4f(qe, qe);
    qn += __shfl_xor_sync(0xffffffffu, qn, 1);
    qn += __shfl_xor_sync(0xffffffffu, qn, 2);
    qn += __shfl_xor_sync(0xffffffffu, qn, 4);
    const float rq = rsqrtf(qn);
    ull qf[8];
    qf[0] = pack2(qa.x * rq, qa.y * rq);  qf[1] = pack2(qa.z * rq, qa.w * rq);
    qf[2] = pack2(qb.x * rq, qb.y * rq);  qf[3] = pack2(qb.z * rq, qb.w * rq);
    qf[4] = pack2(qc.x * rq, qc.y * rq);  qf[5] = pack2(qc.z * rq, qc.w * rq);
    qf[6] = pack2(qe.x * rq, qe.y * rq);  qf[7] = pack2(qe.z * rq, qe.w * rq);

    // packed column accumulators: lane's 16 columns, + and - branches
    ull pp2[8], pm2[8];
#pragma unroll
    for (int i = 0; i < 8; i++) { pp2[i] = 0; pm2[i] = 0; }
    float spa = 0.f, sma = 0.f;

    // ── main loop: one quad (4 rows, 2048B) per warp-iteration ──
    const ulonglong2* __restrict__ e16 = reinterpret_cast<const ulonglong2*>(e);
    int qd = blockIdx.x * WPB + warp;
    const ulonglong2* rp = e16 + ((size_t)qd * 4 + g) * 32 + s;
    const size_t pstride = (size_t)TOTW * 4 * 32;
    for (; qd < NQUAD; qd += TOTW, rp += pstride) {
        ulonglong2 c0 = rp[0];
        ulonglong2 c1 = rp[8];
        ulonglong2 c2 = rp[16];
        ulonglong2 c3 = rp[24];

        ull d2 = 0, n2 = 0;
        d2 = ff2(c0.x, qf[0], d2); n2 = ff2(c0.x, c0.x, n2);
        d2 = ff2(c0.y, qf[1], d2); n2 = ff2(c0.y, c0.y, n2);
        d2 = ff2(c1.x, qf[2], d2); n2 = ff2(c1.x, c1.x, n2);
        d2 = ff2(c1.y, qf[3], d2); n2 = ff2(c1.y, c1.y, n2);
        d2 = ff2(c2.x, qf[4], d2); n2 = ff2(c2.x, c2.x, n2);
        d2 = ff2(c2.y, qf[5], d2); n2 = ff2(c2.y, c2.y, n2);
        d2 = ff2(c3.x, qf[6], d2); n2 = ff2(c3.x, c3.x, n2);
        d2 = ff2(c3.y, qf[7], d2); n2 = ff2(c3.y, c3.y, n2);

        float d = sum2(d2);
        float n = sum2(n2);
        d += __shfl_xor_sync(0xffffffffu, d, 1);
        n += __shfl_xor_sync(0xffffffffu, n, 1);
        d += __shfl_xor_sync(0xffffffffu, d, 2);
        n += __shfl_xor_sync(0xffffffffu, n, 2);
        d += __shfl_xor_sync(0xffffffffu, d, 4);
        n += __shfl_xor_sync(0xffffffffu, n, 4);

        float r = rsqrtf(n);
        float ap = fmaxf(d, 0.f) * r;
        float am = fmaxf(-d, 0.f) * r;
        spa += ap;
        sma += am;
        ull ap2 = pack2(ap, ap);
        ull am2 = pack2(am, am);
        pp2[0] = ff2(ap2, c0.x, pp2[0]);  pm2[0] = ff2(am2, c0.x, pm2[0]);
        pp2[1] = ff2(ap2, c0.y, pp2[1]);  pm2[1] = ff2(am2, c0.y, pm2[1]);
        pp2[2] = ff2(ap2, c1.x, pp2[2]);  pm2[2] = ff2(am2, c1.x, pm2[2]);
        pp2[3] = ff2(ap2, c1.y, pp2[3]);  pm2[3] = ff2(am2, c1.y, pm2[3]);
        pp2[4] = ff2(ap2, c2.x, pp2[4]);  pm2[4] = ff2(am2, c2.x, pm2[4]);
        pp2[5] = ff2(ap2, c2.y, pp2[5]);  pm2[5] = ff2(am2, c2.y, pm2[5]);
        pp2[6] = ff2(ap2, c3.x, pp2[6]);  pm2[6] = ff2(am2, c3.x, pm2[6]);
        pp2[7] = ff2(ap2, c3.y, pp2[7]);  pm2[7] = ff2(am2, c3.y, pm2[7]);
    }

    // ── epilogue: NOW load mu/sigma fragments and pre-dot (loop regs are dead) ──
    const float4* __restrict__ m4p = reinterpret_cast<const float4*>(mu_w);
    const float4* __restrict__ s4p = reinterpret_cast<const float4*>(sigma_w);
    ull t0 = 0, t1 = 0, t2 = 0, t3 = 0;
#pragma unroll
    for (int k = 0; k < 4; k++) {
        float4 m = m4p[s + 8 * k];
        float4 w = s4p[s + 8 * k];
        ull m0 = pack2(m.x, m.y), m1 = pack2(m.z, m.w);
        ull w0 = pack2(w.x, w.y), w1 = pack2(w.z, w.w);
        t0 = ff2(pp2[2 * k], m0, t0);  t0 = ff2(pp2[2 * k + 1], m1, t0);
        t1 = ff2(pm2[2 * k], m0, t1);  t1 = ff2(pm2[2 * k + 1], m1, t1);
        t2 = ff2(pp2[2 * k], w0, t2);  t2 = ff2(pp2[2 * k + 1], w1, t2);
        t3 = ff2(pm2[2 * k], w0, t3);  t3 = ff2(pm2[2 * k + 1], w1, t3);
    }
    float u0 = sum2(t0), u1 = sum2(t1), u2 = sum2(t2), u3 = sum2(t3);
#pragma unroll
    for (int o = 16; o > 0; o >>= 1) {
        u0 += __shfl_xor_sync(0xffffffffu, u0, o);
        u1 += __shfl_xor_sync(0xffffffffu, u1, o);
        u2 += __shfl_xor_sync(0xffffffffu, u2, o);
        u3 += __shfl_xor_sync(0xffffffffu, u3, o);
        spa += __shfl_xor_sync(0xffffffffu, spa, o);
        sma += __shfl_xor_sync(0xffffffffu, sma, o);
    }

    __shared__ float wsum[WPB][6];
    __shared__ int is_last;
    if (lane == 0) {
        wsum[warp][0] = u0;
        wsum[warp][1] = u1;
        wsum[warp][2] = u2;
        wsum[warp][3] = u3;
        wsum[warp][4] = spa * 0.125f;   // each row's a counted by its 8 lanes
        wsum[warp][5] = sma * 0.125f;
    }
    __syncthreads();
    if (tid < 6) {
        float acc = 0.f;
#pragma unroll
        for (int w = 0; w < WPB; w++) acc += wsum[w][tid];
        g_part[tid][blockIdx.x] = acc;
    }
    __threadfence();
    __syncthreads();
    if (tid == 0)
        is_last = (atomicAdd(&g_count, 1) == NBLK - 1) ? 1 : 0;
    __syncthreads();
    if (!is_last) return;

    // ── last block: final 6-scalar reduce + the 8 outputs ──
    __shared__ float tot[6];
    for (int qq = warp; qq < 6; qq += WPB) {
        float acc = 0.f;
#pragma unroll
        for (int i = 0; i < (NBLK + 31) / 32; i++) {
            int j = lane + i * 32;
            if (j < NBLK) acc += __ldcg(&g_part[qq][j]);
        }
#pragma unroll
        for (int o = 16; o > 0; o >>= 1)
            acc += __shfl_xor_sync(0xffffffffu, acc, o);
        if (lane == 0) tot[qq] = acc;
    }
    __syncthreads();
    if (tid < 4) {
        const float Sp = fmaxf(tot[4], 1e-6f);
        const float Sm = fmaxf(tot[5], 1e-6f);
        float wk = w_key[tid];
        float wv = w_value[tid];
        bool pos = (wk > 0.f);
        float dmu = pos ? (tot[0] / Sp) : (tot[1] / Sm);
        float dsg = pos ? (tot[2] / Sp) : (tot[3] / Sm);
        float mu_z = wv * dmu + mu_b[0];
        float x = wv * dsg + sigma_b[0];
        float sig_z = fmaxf(x, 0.f) + log1pf(expf(-fabsf(x)));
        out[tid] = mu_z;
        out[4 + tid] = sig_z;
    }
    if (tid == 0) g_count = 0;  // reset for next graph replay
}

extern "C" void kernel_launch(void* const* d_in, const int* in_sizes, int n_in,
                              void* d_out, int out_size) {
    const float* e       = (const float*)d_in[0];
    const float* w_key   = (const float*)d_in[1];
    const float* w_value = (const float*)d_in[2];
    const float* q       = (const float*)d_in[3];
    const float* mu_w    = (const float*)d_in[4];
    const float* mu_b    = (const float*)d_in[5];
    const float* sigma_w = (const float*)d_in[6];
    const float* sigma_b = (const float*)d_in[7];
    float* out = (float*)d_out;

    fp_r14<<<NBLK, NTHREADS>>>(e, q, mu_w, sigma_w, w_key, w_value, mu_b, sigma_b, out);
}